// round 17
// baseline (speedup 1.0000x reference)
#include <cuda_runtime.h>

// ---------------------------------------------------------------------------
// Fused 2-layer LSTM (relu cell act), B=128, T=512, F=64, U1=256, U2=128.
// 128 persistent CTAs (16 unit-tiles x 8 batch-tiles), 512 threads (16 warps,
// 4 per SMSP for latency hiding), 1 CTA/SM via 116KB smem.
// L1: warp=unit, lane=k-split-32, reg weights (40 f), 2 batch-passes of 8.
// L2: warp=(unit,b-half), lane=k-split-32, smem weights via LDS.128.
// Recursive-halving shfl reduces; lane ends owning one cell (scalar c-state).
// (Resubmission of R15 — previous bench died on container infra, no signal.)
// ---------------------------------------------------------------------------

#define T_STEPS 512
#define FEAT    64
#define U1N     256
#define U2N     128
#define BT      16
#define NBT     8
#define NUT     16

#define AROW    34      // sa row stride (floats) -> banks 2*row, phase-free
#define W2ROW   36      // sw2 row stride: 144B = 16B-aligned for LDS.128

typedef unsigned long long ull;

__device__ float g_h1[T_STEPS][NBT][U1N][BT];
__device__ float g_h2[T_STEPS][NBT][U2N][BT];
__device__ int   g_ctr1[T_STEPS * NBT];
__device__ int   g_ctr2[T_STEPS * NBT];

// ---------------------------------------------------------------------------
__device__ __forceinline__ ull ffma2(ull a, ull b, ull c) {
    ull d; asm("fma.rn.f32x2 %0, %1, %2, %3;" : "=l"(d) : "l"(a), "l"(b), "l"(c));
    return d;
}
__device__ __forceinline__ ull fadd2(ull a, ull b) {
    ull d; asm("add.rn.f32x2 %0, %1, %2;" : "=l"(d) : "l"(a), "l"(b)); return d;
}
__device__ __forceinline__ ull dup2(float v) {
    ull d; asm("mov.b64 %0, {%1, %1};" : "=l"(d) : "f"(v)); return d;
}
__device__ __forceinline__ void unpack2(ull v, float& lo, float& hi) {
    asm("mov.b64 {%0, %1}, %2;" : "=f"(lo), "=f"(hi) : "l"(v));
}
__device__ __forceinline__ float sigm(float z) { return 1.0f / (1.0f + __expf(-z)); }
__device__ __forceinline__ int ld_acquire(const int* p) {
    int v; asm volatile("ld.acquire.gpu.u32 %0, [%1];" : "=r"(v) : "l"(p)); return v;
}
__device__ __forceinline__ void red_release(int* p) {
    asm volatile("red.release.gpu.global.add.u32 [%0], 1;" :: "l"(p) : "memory");
}
__device__ __forceinline__ ull shx(ull v, int d) {
    return __shfl_xor_sync(0xffffffffu, v, d);
}

__global__ void reset_kernel() {
    int i = blockIdx.x * blockDim.x + threadIdx.x;
    if (i < T_STEPS * NBT) { g_ctr1[i] = 0; g_ctr2[i] = 0; }
}

// ---------------------------------------------------------------------------
__global__ __launch_bounds__(512, 1)
void lstm_fused(const float* __restrict__ x,  const float* __restrict__ W1,
                const float* __restrict__ U1, const float* __restrict__ b1,
                const float* __restrict__ W2, const float* __restrict__ U2,
                const float* __restrict__ b2, float* __restrict__ out) {
    extern __shared__ float sm[];
    float* sw2 = sm;                    // [384][36], cols u*4+g (LDS.128)
    float* sa  = sm + 384 * W2ROW;      // [448][34]: 0-63 x, 64-319 h1, 320-447 h2

    const int tid = threadIdx.x;
    const int ui = blockIdx.x, bi = blockIdx.y;
    const int u10 = ui * 16, u20 = ui * 8, b0 = bi * BT;

    const int warp = tid >> 5, lane = tid & 31;
    const int upos2 = warp & 7, bh2 = warp >> 3;   // L2 mapping

    // ---- L1 weights -> registers: k = j*32 + lane, unit = u10 + warp ----
    float w1r[40];
#pragma unroll
    for (int j = 0; j < 10; ++j) {
        int k = j * 32 + lane;
#pragma unroll
        for (int g = 0; g < 4; ++g)
            w1r[j * 4 + g] = (k < FEAT)
                ? W1[k * 1024 + g * 256 + u10 + warp]
                : U1[(k - FEAT) * 1024 + g * 256 + u10 + warp];
    }
    // ---- L2 weights -> smem, [k][u*4+g] ----
    for (int i = tid; i < 384 * 32; i += 512) {
        int k = i >> 5, r = i & 31, uu = r >> 2, g = r & 3;
        float v = (k < U1N) ? W2[k * 512 + g * 128 + u20 + uu]
                            : U2[(k - U1N) * 512 + g * 128 + u20 + uu];
        sw2[k * W2ROW + uu * 4 + g] = v;
    }
    // ---- zero h rows once (t=0 / s=0 read zeros -> uniform loops) ----
    for (int i = tid; i < 384 * AROW; i += 512) sa[64 * AROW + i] = 0.f;

    float bia1[4], bia2[4];
#pragma unroll
    for (int g = 0; g < 4; ++g) {
        bia1[g] = b1[g * 256 + u10 + warp];
        bia2[g] = b2[g * 128 + u20 + upos2];
    }
    float c1[2] = {0.f, 0.f};
    float c2 = 0.f;
    __syncthreads();

    for (int t = 0; t <= T_STEPS; ++t) {
        // ---- x prefetch (LDG in flight across the poll barrier) ----
        float2 xv = make_float2(0.f, 0.f);
        if (t < T_STEPS)
            xv = *(const float2*)(x + ((size_t)(b0 + warp) * T_STEPS + t) * FEAT
                                  + lane * 2);
        if (tid == 0 && t >= 1) {
            const int* p = &g_ctr1[(t - 1) * NBT + bi];
            while (ld_acquire(p) < NUT) {}
        }
        if (tid == 1 && t >= 2) {
            const int* p = &g_ctr2[(t - 2) * NBT + bi];
            while (ld_acquire(p) < NUT) {}
        }
        __syncthreads();

        // ---- stage x (rows 0-63), h1[t-1] (64-319), h2[t-2] (320-447) ----
        if (t < T_STEPS) {
            sa[(lane * 2 + 0) * AROW + warp] = xv.x;
            sa[(lane * 2 + 1) * AROW + warp] = xv.y;
        }
        if (t >= 1) {
            const float4* src = (const float4*)&g_h1[t - 1][bi][0][0];
#pragma unroll
            for (int q = 0; q < 2; ++q) {
                int L = tid + 512 * q;
                float4 v = src[L];
                int u = L >> 2, cc = (L & 3) * 4;
                float* d = sa + (64 + u) * AROW + cc;
                *(float2*)d = make_float2(v.x, v.y);
                *(float2*)(d + 2) = make_float2(v.z, v.w);
            }
        }
        if (t >= 2) {
            const float4* src = (const float4*)&g_h2[t - 2][bi][0][0];
            float4 v = src[tid];
            int u = tid >> 2, cc = (tid & 3) * 4;
            float* d = sa + (320 + u) * AROW + cc;
            *(float2*)d = make_float2(v.x, v.y);
            *(float2*)(d + 2) = make_float2(v.z, v.w);
        }
        __syncthreads();

        const bool k4 = (lane & 16), k3 = (lane & 8);
        const int e = lane & 1;
        const int blq = ((lane >> 3) & 3) * 2 + e;   // local batch within 8-group

        // ================= Layer 1, step t (two 8-batch passes) =============
        if (t < T_STEPS) {
#pragma unroll
            for (int pass = 0; pass < 2; ++pass) {
                ull A[16];
#pragma unroll
                for (int r = 0; r < 16; ++r) A[r] = 0ULL;
                const float* ar = sa + lane * AROW + pass * 8;
#pragma unroll
                for (int j = 0; j < 10; ++j) {
                    ull av[4];
#pragma unroll
                    for (int p = 0; p < 4; ++p)
                        av[p] = *(const ull*)(ar + j * (32 * AROW) + p * 2);
#pragma unroll
                    for (int g = 0; g < 4; ++g) {
                        ull wd = dup2(w1r[j * 4 + g]);
#pragma unroll
                        for (int p = 0; p < 4; ++p)
                            A[g * 4 + p] = ffma2(av[p], wd, A[g * 4 + p]);
                    }
                }
                // reduce: route bp by bits 4,3; full-exchange bits 2,1,0
                ull B[8];
#pragma unroll
                for (int g = 0; g < 4; ++g)
#pragma unroll
                    for (int p = 0; p < 2; ++p) {
                        ull kp = k4 ? A[g * 4 + 2 + p] : A[g * 4 + p];
                        ull sd = k4 ? A[g * 4 + p]     : A[g * 4 + 2 + p];
                        B[g * 2 + p] = fadd2(kp, shx(sd, 16));
                    }
                ull C[4];
#pragma unroll
                for (int g = 0; g < 4; ++g) {
                    ull kp = k3 ? B[g * 2 + 1] : B[g * 2];
                    ull sd = k3 ? B[g * 2]     : B[g * 2 + 1];
                    C[g] = fadd2(kp, shx(sd, 8));
                }
#pragma unroll
                for (int g = 0; g < 4; ++g) {
                    C[g] = fadd2(C[g], shx(C[g], 4));
                    C[g] = fadd2(C[g], shx(C[g], 2));
                    C[g] = fadd2(C[g], shx(C[g], 1));
                }
                float z[4];
#pragma unroll
                for (int g = 0; g < 4; ++g) {
                    float lo, hi; unpack2(C[g], lo, hi);
                    z[g] = e ? hi : lo;
                }
                float ig = sigm(z[0] + bia1[0]);
                float fg = sigm(z[1] + bia1[1]);
                float gg = fmaxf(z[2] + bia1[2], 0.f);
                float og = sigm(z[3] + bia1[3]);
                c1[pass] = fg * c1[pass] + ig * gg;
                float h = og * fmaxf(c1[pass], 0.f);
                if ((lane & 6) == 0)
                    g_h1[t][bi][u10 + warp][pass * 8 + blq] = h;
            }
        }

        // ================= Layer 2, step s = t-1 ============================
        if (t >= 1) {
            const int s = t - 1;
            ull A[16];
#pragma unroll
            for (int r = 0; r < 16; ++r) A[r] = 0ULL;
            const float* ar = sa + (64 + lane) * AROW + bh2 * 8;
            const float* wr = sw2 + lane * W2ROW + upos2 * 4;
#pragma unroll
            for (int j = 0; j < 12; ++j) {
                ull av[4];
#pragma unroll
                for (int p = 0; p < 4; ++p)
                    av[p] = *(const ull*)(ar + j * (32 * AROW) + p * 2);
                float4 wv = *(const float4*)(wr + j * (32 * W2ROW));
                ull w0 = dup2(wv.x), w1d = dup2(wv.y), w2d = dup2(wv.z), w3 = dup2(wv.w);
#pragma unroll
                for (int p = 0; p < 4; ++p) {
                    A[0 * 4 + p] = ffma2(av[p], w0, A[0 * 4 + p]);
                    A[1 * 4 + p] = ffma2(av[p], w1d, A[1 * 4 + p]);
                    A[2 * 4 + p] = ffma2(av[p], w2d, A[2 * 4 + p]);
                    A[3 * 4 + p] = ffma2(av[p], w3, A[3 * 4 + p]);
                }
            }
            ull B[8];
#pragma unroll
            for (int g = 0; g < 4; ++g)
#pragma unroll
                for (int p = 0; p < 2; ++p) {
                    ull kp = k4 ? A[g * 4 + 2 + p] : A[g * 4 + p];
                    ull sd = k4 ? A[g * 4 + p]     : A[g * 4 + 2 + p];
                    B[g * 2 + p] = fadd2(kp, shx(sd, 16));
                }
            ull C[4];
#pragma unroll
            for (int g = 0; g < 4; ++g) {
                ull kp = k3 ? B[g * 2 + 1] : B[g * 2];
                ull sd = k3 ? B[g * 2]     : B[g * 2 + 1];
                C[g] = fadd2(kp, shx(sd, 8));
            }
#pragma unroll
            for (int g = 0; g < 4; ++g) {
                C[g] = fadd2(C[g], shx(C[g], 4));
                C[g] = fadd2(C[g], shx(C[g], 2));
                C[g] = fadd2(C[g], shx(C[g], 1));
            }
            float z[4];
#pragma unroll
            for (int g = 0; g < 4; ++g) {
                float lo, hi; unpack2(C[g], lo, hi);
                z[g] = e ? hi : lo;
            }
            float ig = sigm(z[0] + bia2[0]);
            float fg = sigm(z[1] + bia2[1]);
            float gg = fmaxf(z[2] + bia2[2], 0.f);
            float og = sigm(z[3] + bia2[3]);
            c2 = fg * c2 + ig * gg;
            float h = og * fmaxf(c2, 0.f);
            if ((lane & 6) == 0) {
                int b = bh2 * 8 + blq;
                if (s == T_STEPS - 1) out[(b0 + b) * U2N + u20 + upos2] = h;
                else                  g_h2[s][bi][u20 + upos2][b] = h;
            }
        }

        __syncthreads();
        if (tid == 0 && t < T_STEPS) red_release(&g_ctr1[t * NBT + bi]);
        if (tid == 1 && t >= 1)      red_release(&g_ctr2[(t - 1) * NBT + bi]);
    }
}

// ---------------------------------------------------------------------------
extern "C" void kernel_launch(void* const* d_in, const int* in_sizes, int n_in,
                              void* d_out, int out_size) {
    const float* x  = (const float*)d_in[0];
    const float* W1 = (const float*)d_in[1];
    const float* U1 = (const float*)d_in[2];
    const float* b1 = (const float*)d_in[3];
    const float* W2 = (const float*)d_in[4];
    const float* U2 = (const float*)d_in[5];
    const float* b2 = (const float*)d_in[6];
    float* out = (float*)d_out;

    // smem: (384*36 + 448*34)*4 = 116224 B -> 1 CTA/SM (2x would exceed 228KB)
    const int smem_bytes = (384 * W2ROW + 448 * AROW) * 4;
    cudaFuncSetAttribute(lstm_fused, cudaFuncAttributeMaxDynamicSharedMemorySize,
                         smem_bytes);

    reset_kernel<<<4, 1024>>>();
    lstm_fused<<<dim3(NUT, NBT), 512, smem_bytes>>>(x, W1, U1, b1, W2, U2, b2, out);
}